// round 3
// baseline (speedup 1.0000x reference)
#include <cuda_runtime.h>
#include <cuda_bf16.h>
#include <math.h>
#include <stdint.h>

#define BB   2
#define SS   2048
#define DD   2048
#define HH   16
#define KVH  8
#define GG   2
#define HD   128
#define SCALE 0.08838834764831845f

typedef __nv_bfloat16 bf16;
typedef __nv_bfloat162 bf162;

// ---------------- persistent scratch (device globals) ----------------
__device__ float g_q[8388608];            // (B,S,H,HD) fp32 pre-norm
__device__ float g_k[4194304];            // (B,S,KV,HD) fp32 pre-norm
__device__ bf16 xs_h[8388608],  xs_l[8388608];    // X split
__device__ bf16 wqs_h[4194304], wqs_l[4194304];
__device__ bf16 wks_h[2097152], wks_l[2097152];
__device__ bf16 wvs_h[2097152], wvs_l[2097152];
__device__ bf16 wos_h[4194304], wos_l[4194304];
__device__ bf16 qs_h[8388608],  qs_l[8388608];    // Q post norm+rope
__device__ bf16 ks_h[4194304],  ks_l[4194304];
__device__ bf16 vs_h[4194304],  vs_l[4194304];
__device__ bf16 os_h[8388608],  os_l[8388608];    // AV output
__device__ bf16 ps_h[134217728], ps_l[134217728]; // attn probs split

// ---------------- PTX helpers ----------------
__device__ __forceinline__ uint32_t smaddr(const void* p) {
    return (uint32_t)__cvta_generic_to_shared(p);
}
__device__ __forceinline__ void cpa16(uint32_t d, const void* s) {
    asm volatile("cp.async.cg.shared.global [%0], [%1], 16;" :: "r"(d), "l"(s));
}
__device__ __forceinline__ void cp_commit() { asm volatile("cp.async.commit_group;"); }
__device__ __forceinline__ void cp_wait1()  { asm volatile("cp.async.wait_group 1;"); }
__device__ __forceinline__ void cp_wait0()  { asm volatile("cp.async.wait_group 0;"); }

__device__ __forceinline__ void ldsm_x4(uint32_t* r, uint32_t addr) {
    asm volatile("ldmatrix.sync.aligned.m8n8.x4.shared.b16 {%0,%1,%2,%3}, [%4];"
        : "=r"(r[0]), "=r"(r[1]), "=r"(r[2]), "=r"(r[3]) : "r"(addr));
}
__device__ __forceinline__ void ldsm_x2(uint32_t* r, uint32_t addr) {
    asm volatile("ldmatrix.sync.aligned.m8n8.x2.shared.b16 {%0,%1}, [%2];"
        : "=r"(r[0]), "=r"(r[1]) : "r"(addr));
}
__device__ __forceinline__ void ldsm_x2t(uint32_t* r, uint32_t addr) {
    asm volatile("ldmatrix.sync.aligned.m8n8.x2.trans.shared.b16 {%0,%1}, [%2];"
        : "=r"(r[0]), "=r"(r[1]) : "r"(addr));
}
__device__ __forceinline__ void mma_bf16(float* c, const uint32_t* a, const uint32_t* b) {
    asm volatile(
        "mma.sync.aligned.m16n8k16.row.col.f32.bf16.bf16.f32 "
        "{%0,%1,%2,%3}, {%4,%5,%6,%7}, {%8,%9}, {%0,%1,%2,%3};"
        : "+f"(c[0]), "+f"(c[1]), "+f"(c[2]), "+f"(c[3])
        : "r"(a[0]), "r"(a[1]), "r"(a[2]), "r"(a[3]), "r"(b[0]), "r"(b[1]));
}
__device__ __forceinline__ void split2(float x, float y, bf162& h, bf162& l) {
    h = __floats2bfloat162_rn(x, y);
    l = __floats2bfloat162_rn(x - __low2float(h), y - __high2float(h));
}

// ---------------------------------------------------------------------------
// bf16x3 GEMM, pre-split operands, cp.async double-buffered.
// C(128x128) tile: BTRANS: A[M,K] x B[N,K]^T ; !BTRANS: A[M,K] x B[K,N]
// EPI 0: fp32*alpha -> C. EPI 1: split bf16 -> Ch/Cl.
// ---------------------------------------------------------------------------
#define AROW 40
#define BROWN 136

template<bool BTRANS, int EPI>
__device__ __forceinline__ void gemm_core(
    const bf16* __restrict__ Ah, const bf16* __restrict__ Al, int lda,
    const bf16* __restrict__ Bh, const bf16* __restrict__ Bl, int ldb,
    float* __restrict__ C, bf16* __restrict__ Ch, bf16* __restrict__ Cl,
    int ldc, int K, float alpha)
{
    extern __shared__ __align__(16) bf16 sm[];
    constexpr int APL  = 128 * AROW;                       // 5120 elems
    constexpr int BPLE = BTRANS ? 128 * AROW : 32 * BROWN; // 5120 / 4352

    const int tid  = threadIdx.x;
    const int lane = tid & 31;
    const int wid  = tid >> 5;
    const int wm   = (wid >> 2) << 6;
    const int wn   = (wid & 3) << 5;

    float acc[4][4][4];
#pragma unroll
    for (int i = 0; i < 4; ++i)
#pragma unroll
        for (int j = 0; j < 4; ++j)
#pragma unroll
            for (int l = 0; l < 4; ++l) acc[i][j][l] = 0.f;

    auto stage = [&](int buf, int k0) {
        bf16* dAh = sm + buf * APL;
        bf16* dAl = sm + 2 * APL + buf * APL;
        bf16* dBh = sm + 4 * APL + buf * BPLE;
        bf16* dBl = sm + 4 * APL + 2 * BPLE + buf * BPLE;
        int task = tid;
#pragma unroll
        for (int p = 0; p < 2; ++p, task += 256) {
            int r = task >> 2, sg = (task & 3) << 3;
            size_t go = (size_t)r * lda + k0 + sg;
            cpa16(smaddr(dAh + r * AROW + sg), Ah + go);
            cpa16(smaddr(dAl + r * AROW + sg), Al + go);
        }
        task = tid;
        if (BTRANS) {
#pragma unroll
            for (int p = 0; p < 2; ++p, task += 256) {
                int r = task >> 2, sg = (task & 3) << 3;
                size_t go = (size_t)r * ldb + k0 + sg;
                cpa16(smaddr(dBh + r * AROW + sg), Bh + go);
                cpa16(smaddr(dBl + r * AROW + sg), Bl + go);
            }
        } else {
#pragma unroll
            for (int p = 0; p < 2; ++p, task += 256) {
                int r = task >> 4, sg = (task & 15) << 3;
                size_t go = (size_t)(k0 + r) * ldb + sg;
                cpa16(smaddr(dBh + r * BROWN + sg), Bh + go);
                cpa16(smaddr(dBl + r * BROWN + sg), Bl + go);
            }
        }
        cp_commit();
    };

    const int nch = K >> 5;
    stage(0, 0);
    for (int i = 0; i < nch; ++i) {
        const bool more = (i + 1 < nch);
        if (more) stage((i + 1) & 1, (i + 1) << 5);
        if (more) cp_wait1(); else cp_wait0();
        __syncthreads();

        const bf16* pAh = sm + (i & 1) * APL;
        const bf16* pAl = sm + 2 * APL + (i & 1) * APL;
        const bf16* pBh = sm + 4 * APL + (i & 1) * BPLE;
        const bf16* pBl = sm + 4 * APL + 2 * BPLE + (i & 1) * BPLE;

#pragma unroll
        for (int ks = 0; ks < 2; ++ks) {
            uint32_t af[4][4], bh[4][2], bl[4][2];
            const int arow = lane & 15;
            const int akb  = ks * 32 + ((lane >> 4) << 4);

#pragma unroll
            for (int mt = 0; mt < 4; ++mt)
                ldsm_x4(af[mt], smaddr(pAh + (wm + mt * 16 + arow) * AROW) + akb);
#pragma unroll
            for (int nt = 0; nt < 4; ++nt) {
                if (BTRANS)
                    ldsm_x2(bh[nt], smaddr(pBh + (wn + nt * 8 + (lane & 7)) * AROW)
                                    + ks * 32 + (((lane >> 3) & 1) << 4));
                else
                    ldsm_x2t(bh[nt], smaddr(pBh + (ks * 16 + (lane & 15)) * BROWN + wn + nt * 8));
            }
#pragma unroll
            for (int mt = 0; mt < 4; ++mt)
#pragma unroll
                for (int nt = 0; nt < 4; ++nt) mma_bf16(acc[mt][nt], af[mt], bh[nt]);

#pragma unroll
            for (int nt = 0; nt < 4; ++nt) {
                if (BTRANS)
                    ldsm_x2(bl[nt], smaddr(pBl + (wn + nt * 8 + (lane & 7)) * AROW)
                                    + ks * 32 + (((lane >> 3) & 1) << 4));
                else
                    ldsm_x2t(bl[nt], smaddr(pBl + (ks * 16 + (lane & 15)) * BROWN + wn + nt * 8));
            }
#pragma unroll
            for (int mt = 0; mt < 4; ++mt)
#pragma unroll
                for (int nt = 0; nt < 4; ++nt) mma_bf16(acc[mt][nt], af[mt], bl[nt]);

#pragma unroll
            for (int mt = 0; mt < 4; ++mt)
                ldsm_x4(af[mt], smaddr(pAl + (wm + mt * 16 + arow) * AROW) + akb);
#pragma unroll
            for (int mt = 0; mt < 4; ++mt)
#pragma unroll
                for (int nt = 0; nt < 4; ++nt) mma_bf16(acc[mt][nt], af[mt], bh[nt]);
        }
        __syncthreads();
    }

#pragma unroll
    for (int mt = 0; mt < 4; ++mt) {
#pragma unroll
        for (int nt = 0; nt < 4; ++nt) {
            int r = wm + mt * 16 + (lane >> 2);
            int c = wn + nt * 8 + ((lane & 3) << 1);
            if (EPI == 0) {
                float2 v0 = make_float2(alpha * acc[mt][nt][0], alpha * acc[mt][nt][1]);
                float2 v1 = make_float2(alpha * acc[mt][nt][2], alpha * acc[mt][nt][3]);
                *(float2*)&C[(size_t)r * ldc + c]       = v0;
                *(float2*)&C[(size_t)(r + 8) * ldc + c] = v1;
            } else {
                bf162 h0, l0, h1, l1;
                split2(acc[mt][nt][0], acc[mt][nt][1], h0, l0);
                split2(acc[mt][nt][2], acc[mt][nt][3], h1, l1);
                *(bf162*)&Ch[(size_t)r * ldc + c]       = h0;
                *(bf162*)&Cl[(size_t)r * ldc + c]       = l0;
                *(bf162*)&Ch[(size_t)(r + 8) * ldc + c] = h1;
                *(bf162*)&Cl[(size_t)(r + 8) * ldc + c] = l1;
            }
        }
    }
}

// ---------------- GEMM kernel wrappers ----------------
__global__ __launch_bounds__(256, 2) void proj_f32_k(
    const bf16* Ah, const bf16* Al, int lda,
    const bf16* Bh, const bf16* Bl, int ldb,
    float* C, int ldc, int K)
{
    size_t ao = (size_t)blockIdx.y * 128 * lda;
    size_t bo = (size_t)blockIdx.x * 128 * ldb;
    gemm_core<true, 0>(Ah + ao, Al + ao, lda, Bh + bo, Bl + bo, ldb,
                       C + (size_t)blockIdx.y * 128 * ldc + blockIdx.x * 128,
                       nullptr, nullptr, ldc, K, 1.0f);
}

__global__ __launch_bounds__(256, 2) void proj_split_k(
    const bf16* Ah, const bf16* Al, int lda,
    const bf16* Bh, const bf16* Bl, int ldb,
    bf16* Ch, bf16* Cl, int ldc, int K)
{
    size_t ao = (size_t)blockIdx.y * 128 * lda;
    size_t bo = (size_t)blockIdx.x * 128 * ldb;
    size_t co = (size_t)blockIdx.y * 128 * ldc + blockIdx.x * 128;
    gemm_core<true, 1>(Ah + ao, Al + ao, lda, Bh + bo, Bl + bo, ldb,
                       nullptr, Ch + co, Cl + co, ldc, K, 1.0f);
}

__global__ __launch_bounds__(256, 2) void score_k(
    const bf16* qh, const bf16* ql, const bf16* kh, const bf16* kl,
    float* __restrict__ attn)
{
    if (blockIdx.x > blockIdx.y) return;
    const int bh = blockIdx.z;
    const int h = bh % HH, b = bh / HH, kv = h / GG;
    size_t ao = ((size_t)b * SS * HH + h) * HD + (size_t)blockIdx.y * 128 * (HH * HD);
    size_t bo = ((size_t)b * SS * KVH + kv) * HD + (size_t)blockIdx.x * 128 * (KVH * HD);
    float* C = attn + (size_t)bh * SS * SS
                    + (size_t)blockIdx.y * 128 * SS + (size_t)blockIdx.x * 128;
    gemm_core<true, 0>(qh + ao, ql + ao, HH * HD, kh + bo, kl + bo, KVH * HD,
                       C, nullptr, nullptr, SS, HD, SCALE);
}

__global__ __launch_bounds__(256, 2) void av_k(
    const bf16* ph, const bf16* pl, const bf16* vh, const bf16* vl,
    bf16* oh, bf16* ol)
{
    const int bh = blockIdx.z;
    const int h = bh % HH, b = bh / HH, kv = h / GG;
    size_t ao = (size_t)bh * SS * SS + (size_t)blockIdx.y * 128 * SS;
    size_t bo = ((size_t)b * SS * KVH + kv) * HD;
    size_t co = ((size_t)b * SS * HH + h) * HD + (size_t)blockIdx.y * 128 * (HH * HD);
    const int K = (int)blockIdx.y * 128 + 128;
    gemm_core<false, 1>(ph + ao, pl + ao, SS, vh + bo, vl + bo, KVH * HD,
                        nullptr, oh + co, ol + co, HH * HD, K, 1.0f);
}

// ---------------- split fp32 -> bf16 hi/lo ----------------
__global__ __launch_bounds__(256) void split_kernel(
    const float* __restrict__ in, bf16* __restrict__ hi, bf16* __restrict__ lo, int n)
{
    int i = (blockIdx.x * 256 + threadIdx.x) * 4;
    if (i >= n) return;
    float4 v = *(const float4*)(in + i);
    bf162 h0, l0, h1, l1;
    split2(v.x, v.y, h0, l0);
    split2(v.z, v.w, h1, l1);
    *(bf162*)(hi + i)     = h0;
    *(bf162*)(hi + i + 2) = h1;
    *(bf162*)(lo + i)     = l0;
    *(bf162*)(lo + i + 2) = l1;
}

// ---------------- RMSNorm + RoPE -> split bf16 ----------------
__global__ __launch_bounds__(128) void normrope_split(
    const float* __restrict__ in, bf16* __restrict__ oh, bf16* __restrict__ ol,
    const float* __restrict__ w,
    const float* __restrict__ cosb, const float* __restrict__ sinb, int nheads)
{
    const int idx = blockIdx.x;
    const int h = idx % nheads;
    const int s = (idx / nheads) % SS;
    const int b = idx / (nheads * SS);
    const int t = threadIdx.x;

    size_t off = (((size_t)b * SS + s) * nheads + h) * HD;
    float v = in[off + t];

    float ss = v * v;
#pragma unroll
    for (int o = 16; o; o >>= 1) ss += __shfl_xor_sync(0xffffffffu, ss, o);

    __shared__ float ws[4];
    __shared__ float sh[128];
    const int lane = t & 31, wid = t >> 5;
    if (lane == 0) ws[wid] = ss;
    __syncthreads();
    float var = (ws[0] + ws[1] + ws[2] + ws[3]) * (1.0f / HD);
    float xn = v * rsqrtf(var + 1e-6f) * w[t];
    sh[t] = xn;
    __syncthreads();
    float rot = (t < 64) ? -sh[t + 64] : sh[t - 64];

    const float* cp = cosb + ((size_t)b * SS + s) * HD;
    const float* sp = sinb + ((size_t)b * SS + s) * HD;
    float r = xn * cp[t] + rot * sp[t];
    bf16 hh = __float2bfloat16(r);
    oh[off + t] = hh;
    ol[off + t] = __float2bfloat16(r - __bfloat162float(hh));
}

// ---------------- softmax (causal) + P split emit ----------------
__global__ __launch_bounds__(256) void softmax_kernel(
    float* __restrict__ attn, bf16* __restrict__ ph, bf16* __restrict__ pl)
{
    __shared__ float buf[SS];
    __shared__ float red[256];
    const int row = blockIdx.x;
    const int qi = row & (SS - 1);
    const int valid = qi + 1;
    const int span = ((qi >> 7) + 1) << 7;     // tile-rounded; == AV read extent
    float* base = attn + (size_t)row * SS;
    const int tid = threadIdx.x;

    float m = -1e30f;
    for (int t = tid * 4; t < span; t += 1024) {
        float4 v = *(const float4*)(base + t);
        v.x = (t + 0 < valid) ? v.x : -1e30f;
        v.y = (t + 1 < valid) ? v.y : -1e30f;
        v.z = (t + 2 < valid) ? v.z : -1e30f;
        v.w = (t + 3 < valid) ? v.w : -1e30f;
        *(float4*)(buf + t) = v;
        m = fmaxf(m, fmaxf(fmaxf(v.x, v.y), fmaxf(v.z, v.w)));
    }
    red[tid] = m; __syncthreads();
    for (int s2 = 128; s2; s2 >>= 1) {
        if (tid < s2) red[tid] = fmaxf(red[tid], red[tid + s2]);
        __syncthreads();
    }
    const float mx = red[0];
    __syncthreads();

    float sum = 0.f;
    for (int t = tid * 4; t < span; t += 1024) {
        float4 v = *(const float4*)(buf + t);
        v.x = expf(v.x - mx); v.y = expf(v.y - mx);
        v.z = expf(v.z - mx); v.w = expf(v.w - mx);
        *(float4*)(buf + t) = v;
        sum += v.x + v.y + v.z + v.w;
    }
    red[tid] = sum; __syncthreads();
    for (int s2 = 128; s2; s2 >>= 1) {
        if (tid < s2) red[tid] += red[tid + s2];
        __syncthreads();
    }
    const float inv = 1.0f / red[0];

    // fp32 final (full row, zeros beyond valid)
    for (int t = tid * 4; t < SS; t += 1024) {
        float4 o;
        o.x = (t + 0 < span) ? buf[t + 0] * inv : 0.f;
        o.y = (t + 1 < span) ? buf[t + 1] * inv : 0.f;
        o.z = (t + 2 < span) ? buf[t + 2] * inv : 0.f;
        o.w = (t + 3 < span) ? buf[t + 3] * inv : 0.f;
        *(float4*)(base + t) = o;
    }
    // bf16 hi/lo planes over [0, span)
    bf16* hp = ph + (size_t)row * SS;
    bf16* lp = pl + (size_t)row * SS;
    for (int t = tid * 2; t < span; t += 512) {
        bf162 h, l;
        split2(buf[t] * inv, buf[t + 1] * inv, h, l);
        *(bf162*)(hp + t) = h;
        *(bf162*)(lp + t) = l;
    }
}

// ---------------- launch ----------------
extern "C" void kernel_launch(void* const* d_in, const int* in_sizes, int n_in,
                              void* d_out, int out_size)
{
    const float* x    = (const float*)d_in[0];
    const float* cosb = (const float*)d_in[1];
    const float* sinb = (const float*)d_in[2];
    const float* wq   = (const float*)d_in[4];
    const float* wk   = (const float*)d_in[5];
    const float* wv   = (const float*)d_in[6];
    const float* wo   = (const float*)d_in[7];
    const float* qw   = (const float*)d_in[8];
    const float* kw   = (const float*)d_in[9];

    float* out  = (float*)d_out;
    float* attn = out + (size_t)BB * SS * HH * HD;

    float *pq, *pk;
    bf16 *pxh, *pxl, *pwqh, *pwql, *pwkh, *pwkl, *pwvh, *pwvl, *pwoh, *pwol;
    bf16 *pqh, *pql, *pkh, *pkl, *pvh, *pvl, *poh, *pol, *pph, *ppl;
    cudaGetSymbolAddress((void**)&pq, g_q);
    cudaGetSymbolAddress((void**)&pk, g_k);
    cudaGetSymbolAddress((void**)&pxh, xs_h);  cudaGetSymbolAddress((void**)&pxl, xs_l);
    cudaGetSymbolAddress((void**)&pwqh, wqs_h); cudaGetSymbolAddress((void**)&pwql, wqs_l);
    cudaGetSymbolAddress((void**)&pwkh, wks_h); cudaGetSymbolAddress((void**)&pwkl, wks_l);
    cudaGetSymbolAddress((void**)&pwvh, wvs_h); cudaGetSymbolAddress((void**)&pwvl, wvs_l);
    cudaGetSymbolAddress((void**)&pwoh, wos_h); cudaGetSymbolAddress((void**)&pwol, wos_l);
    cudaGetSymbolAddress((void**)&pqh, qs_h);   cudaGetSymbolAddress((void**)&pql, qs_l);
    cudaGetSymbolAddress((void**)&pkh, ks_h);   cudaGetSymbolAddress((void**)&pkl, ks_l);
    cudaGetSymbolAddress((void**)&pvh, vs_h);   cudaGetSymbolAddress((void**)&pvl, vs_l);
    cudaGetSymbolAddress((void**)&poh, os_h);   cudaGetSymbolAddress((void**)&pol, os_l);
    cudaGetSymbolAddress((void**)&pph, ps_h);   cudaGetSymbolAddress((void**)&ppl, ps_l);

    // opt-in >48KB dynamic smem (sticky per function; capture-safe query/set)
    const int SM_NT = 81920;   // 4 A planes + 4 B planes (NT), 2 buffers
    const int SM_NN = 75776;
    cudaFuncSetAttribute(proj_f32_k,  cudaFuncAttributeMaxDynamicSharedMemorySize, SM_NT);
    cudaFuncSetAttribute(proj_split_k,cudaFuncAttributeMaxDynamicSharedMemorySize, SM_NT);
    cudaFuncSetAttribute(score_k,     cudaFuncAttributeMaxDynamicSharedMemorySize, SM_NT);
    cudaFuncSetAttribute(av_k,        cudaFuncAttributeMaxDynamicSharedMemorySize, SM_NN);

    const int BS = BB * SS;   // 4096
    dim3 blk(256);

    // operand splits
    split_kernel<<<(BB*SS*DD/4 + 255)/256, 256>>>(x,  pxh,  pxl,  BB*SS*DD);
    split_kernel<<<(HH*HD*DD/4 + 255)/256, 256>>>(wq, pwqh, pwql, HH*HD*DD);
    split_kernel<<<(KVH*HD*DD/4 + 255)/256, 256>>>(wk, pwkh, pwkl, KVH*HD*DD);
    split_kernel<<<(KVH*HD*DD/4 + 255)/256, 256>>>(wv, pwvh, pwvl, KVH*HD*DD);
    split_kernel<<<(DD*HH*HD/4 + 255)/256, 256>>>(wo, pwoh, pwol, DD*HH*HD);

    // projections
    proj_f32_k<<<dim3((HH*HD)/128, BS/128), blk, SM_NT>>>(
        pxh, pxl, DD, pwqh, pwql, DD, pq, HH*HD, DD);
    proj_f32_k<<<dim3((KVH*HD)/128, BS/128), blk, SM_NT>>>(
        pxh, pxl, DD, pwkh, pwkl, DD, pk, KVH*HD, DD);
    proj_split_k<<<dim3((KVH*HD)/128, BS/128), blk, SM_NT>>>(
        pxh, pxl, DD, pwvh, pwvl, DD, pvh, pvl, KVH*HD, DD);

    // norm + rope -> split planes
    normrope_split<<<BB*SS*HH, 128>>>(pq, pqh, pql, qw, cosb, sinb, HH);
    normrope_split<<<BB*SS*KVH, 128>>>(pk, pkh, pkl, kw, cosb, sinb, KVH);

    // attention
    score_k<<<dim3(SS/128, SS/128, BB*HH), blk, SM_NT>>>(pqh, pql, pkh, pkl, attn);
    softmax_kernel<<<BB*HH*SS, 256>>>(attn, pph, ppl);
    av_k<<<dim3(1, SS/128, BB*HH), blk, SM_NN>>>(pph, ppl, pvh, pvl, poh, pol);

    // output projection
    proj_f32_k<<<dim3(DD/128, BS/128), blk, SM_NT>>>(
        poh, pol, HH*HD, pwoh, pwol, HH*HD, out, DD, HH*HD);
}